// round 7
// baseline (speedup 1.0000x reference)
#include <cuda_runtime.h>
#include <cuda_bf16.h>
#include <cstdint>

// Problem shapes (fixed by the dataset)
#define S_LEN 2048
#define BATCH 16
#define DDIM  2048

// Stage-1 tiling
#define OTILE   512                 // output rows per block (4 per thread)
#define KSPLIT  64
#define KCHUNK  (DDIM / KSPLIT)     // 32 d per block
#define SUBK    16                  // d per smem-resident sub-chunk
#define NSUB    (KCHUNK / SUBK)     // 2
#define WSTRIDE 17                  // odd -> conflict-free scalar w reads
#define SPAD    20                  // sS row stride (80B, 16B-aligned LDS.128)

// Scratch (device globals: allocation-free).
// g_part layout: [kc][o][b]
__device__ float g_part[KSPLIT * DDIM * BATCH];   // 8 MB
__device__ float g_altered[BATCH * DDIM];         // [b][o], 128 KB

__device__ __forceinline__ void ffma2(uint64_t& d, uint64_t a, uint64_t b) {
    asm("fma.rn.f32x2 %0, %1, %2, %0;" : "+l"(d) : "l"(a), "l"(b));
}

// ---------------------------------------------------------------------------
// Kernel 1a: partial[kc][o][b] = sum_{d in chunk kc} state[b][d] * W[o][d]
// Thread computes a 4o x 16b register tile (32 packed f32x2 accumulators) ->
// per d: 4 scalar LDS (W rows t+128i, stride 17 => bank (t+d)%32 conflict-
// free) + 4 broadcast LDS.128 (state pairs) + 32 FFMA2.  8 LDS per 64 MACs:
// 2.5x fewer shared-pipe instructions per MAC than the 1o x 16b version,
// which was pinned at the 4-cyc/SM LDS crossbar floor.
// ---------------------------------------------------------------------------
__global__ void __launch_bounds__(128)
stage1_part(const float* __restrict__ state,
            const float* __restrict__ W)
{
    __shared__ float sW[OTILE][WSTRIDE];   // 512 x 17 x 4B = 34.8 KB
    __shared__ float sS[KCHUNK][SPAD];     // 32 x 20 x 4B  = 2.5 KB

    const int t     = threadIdx.x;         // 0..127
    const int obase = blockIdx.x * OTILE;
    const int kc    = blockIdx.y;
    const int d0    = kc * KCHUNK;

    // --- Stage state chunk (16 b x 32 d), transposed to sS[d][b].
    // thread: b = t>>3, c4 = t&7 -> coalesced float4 LDG over d.
    {
        const int b  = t >> 3;
        const int c4 = t & 7;
        const float4 v = *(const float4*)(state + b * DDIM + d0 + c4 * 4);
        sS[c4 * 4 + 0][b] = v.x;
        sS[c4 * 4 + 1][b] = v.y;
        sS[c4 * 4 + 2][b] = v.z;
        sS[c4 * 4 + 3][b] = v.w;
    }

    uint64_t acc[4][8];                    // [o][b-pair] packed f32x2
#pragma unroll
    for (int i = 0; i < 4; ++i)
#pragma unroll
        for (int j = 0; j < 8; ++j) acc[i][j] = 0ull;

#pragma unroll
    for (int sc = 0; sc < NSUB; ++sc) {
        // --- Cooperative coalesced load of W sub-tile (512 rows x 16 d).
        // 2048 float4 / 128 thr = 16 each; warp = 8 rows x 4 c4 (64B runs).
#pragma unroll
        for (int j = 0; j < 16; ++j) {
            const int g  = j * 128 + t;
            const int r  = g >> 2;
            const int c4 = g & 3;
            const float4 v = *(const float4*)(W + (long)(obase + r) * DDIM
                                              + d0 + sc * SUBK + c4 * 4);
            sW[r][c4 * 4 + 0] = v.x;
            sW[r][c4 * 4 + 1] = v.y;
            sW[r][c4 * 4 + 2] = v.z;
            sW[r][c4 * 4 + 3] = v.w;
        }
        __syncthreads();

#pragma unroll
        for (int d = 0; d < SUBK; ++d) {
            const int dl = sc * SUBK + d;
            // W scalars for the 4 rows (conflict-free: bank (t+d)%32).
            uint64_t wp[4];
#pragma unroll
            for (int i = 0; i < 4; ++i) {
                const float w = sW[t + 128 * i][d];
                asm("mov.b64 %0, {%1, %1};" : "=l"(wp[i]) : "r"(__float_as_uint(w)));
            }
            // state: 16 b as 8 packed pairs (broadcast LDS.128, N=1).
            const ulonglong2 q0 = *(const ulonglong2*)&sS[dl][0];
            const ulonglong2 q1 = *(const ulonglong2*)&sS[dl][4];
            const ulonglong2 q2 = *(const ulonglong2*)&sS[dl][8];
            const ulonglong2 q3 = *(const ulonglong2*)&sS[dl][12];
#pragma unroll
            for (int i = 0; i < 4; ++i) {
                ffma2(acc[i][0], wp[i], q0.x);  ffma2(acc[i][1], wp[i], q0.y);
                ffma2(acc[i][2], wp[i], q1.x);  ffma2(acc[i][3], wp[i], q1.y);
                ffma2(acc[i][4], wp[i], q2.x);  ffma2(acc[i][5], wp[i], q2.y);
                ffma2(acc[i][6], wp[i], q3.x);  ffma2(acc[i][7], wp[i], q3.y);
            }
        }
        __syncthreads();   // protect sW before next sub-chunk overwrite
    }

    // --- Unpack and store: per o-row 16 consecutive floats (4 STG.128).
#pragma unroll
    for (int i = 0; i < 4; ++i) {
        float res[16];
#pragma unroll
        for (int j = 0; j < 8; ++j)
            asm("mov.b64 {%0, %1}, %2;"
                : "=f"(res[2 * j]), "=f"(res[2 * j + 1]) : "l"(acc[i][j]));
        const int o = obase + t + 128 * i;
        float* dst = g_part + ((long)kc * DDIM + o) * BATCH;
#pragma unroll
        for (int q = 0; q < 4; ++q)
            *(float4*)(dst + q * 4) =
                make_float4(res[q * 4], res[q * 4 + 1], res[q * 4 + 2], res[q * 4 + 3]);
    }
}

// ---------------------------------------------------------------------------
// Kernel 1b: altered[b][o] = bias[o] + sum_kc partial[kc][o][b]
// 8 MB streamed, fully coalesced reads; deterministic order.
// ---------------------------------------------------------------------------
__global__ void __launch_bounds__(256)
stage1_reduce(const float* __restrict__ bias)
{
    const int n = blockIdx.x * 256 + threadIdx.x;   // 0..32767
    const int o = n >> 4;
    const int b = n & 15;
    float v = bias[o];
#pragma unroll
    for (int kc = 0; kc < KSPLIT; ++kc)
        v += g_part[(long)kc * DDIM * BATCH + n];
    g_altered[b * DDIM + o] = v;
}

// ---------------------------------------------------------------------------
// Kernel 2: weights[b][s] = sum_d altered[b][d] * enc[s][b][d]
// At the LTS chip cap (~6.3 TB/s) -- unchanged.
// ---------------------------------------------------------------------------
__global__ void __launch_bounds__(256, 8)
stage2_dots(const float* __restrict__ enc,
            float* __restrict__ out)
{
    __shared__ float alt[DDIM];

    const int tid    = threadIdx.x;
    const int warpId = tid >> 5;
    const int lane   = tid & 31;
    const int b      = blockIdx.y;
    const int s      = blockIdx.x * 8 + warpId;

#pragma unroll
    for (int j = 0; j < 2; ++j) {
        int f4 = tid + j * 256;
        *(float4*)&alt[f4 * 4] = *(const float4*)(g_altered + b * DDIM + f4 * 4);
    }
    __syncthreads();

    const float* row = enc + ((long)s * BATCH + b) * DDIM;

    float4 acc = make_float4(0.f, 0.f, 0.f, 0.f);
#pragma unroll
    for (int i = 0; i < 16; ++i) {
        const int d = i * 128 + lane * 4;
        const float4 e = *(const float4*)(row + d);
        const float4 a = *(const float4*)&alt[d];
        acc.x += e.x * a.x;
        acc.y += e.y * a.y;
        acc.z += e.z * a.z;
        acc.w += e.w * a.w;
    }

    float tt = (acc.x + acc.y) + (acc.z + acc.w);
#pragma unroll
    for (int off = 16; off > 0; off >>= 1)
        tt += __shfl_down_sync(0xFFFFFFFFu, tt, off);

    if (lane == 0)
        out[b * S_LEN + s] = tt;   // output shape [B, S]
}

extern "C" void kernel_launch(void* const* d_in, const int* in_sizes, int n_in,
                              void* d_out, int out_size)
{
    const float* enc   = (const float*)d_in[0];  // [S, B, D]
    const float* state = (const float*)d_in[1];  // [B, D]
    const float* W     = (const float*)d_in[2];  // [D, D]
    const float* bias  = (const float*)d_in[3];  // [D]
    float* out         = (float*)d_out;          // [B, S]

    stage1_part<<<dim3(DDIM / OTILE, KSPLIT), 128>>>(state, W);
    stage1_reduce<<<(BATCH * DDIM) / 256, 256>>>(bias);
    stage2_dots<<<dim3(S_LEN / 8, BATCH), 256>>>(enc, out);
}